// round 5
// baseline (speedup 1.0000x reference)
#include <cuda_runtime.h>
#include <cstdint>

#define BB 32
#define NN 512
#define HH 8
#define DH 8
#define DO 32
#define FIN 16
#define ALPHAC 0.2f
#define FULLM 0xffffffffu
#define EMAX 128          // fast-path edge cap (P(cnt>128) ~ 0; fallback is correct)
#define KSPLIT 256        // k4: 256 splits x 64 rows
#define NSPLIT 2          // k4: 2 n-tiles x 256 cols

// ---------- scratch (static device globals; no allocation) ----------
__device__ __align__(16) float g_Wh2[BB*NN*64];   // 8 MB  [b][n][h*8+d]
__device__ __align__(16) float g_f1v[BB*NN*HH];
__device__ __align__(16) float g_f2v[BB*NN*HH];
__device__ unsigned short g_edges[(size_t)BB*NN*NN];
__device__ int   g_cnt[BB*NN];
__device__ __align__(16) float g_Who[BB*NN*DO];
__device__ float g_g1[BB*NN];
__device__ float g_g2[BB*NN];
__device__ __align__(16) float g_out[BB*NN*DO];   // 2 MB == A[32][16384]
__device__ __align__(16) float g_part[(size_t)KSPLIT * BB * NN];  // 16 MB partials

__device__ __forceinline__ uint64_t packf2(float lo, float hi) {
    uint64_t p;
    asm("mov.b64 %0, {%1, %2};" : "=l"(p) : "f"(lo), "f"(hi));
    return p;
}
__device__ __forceinline__ void unpackf2(float& lo, float& hi, uint64_t p) {
    asm("mov.b64 {%0, %1}, %2;" : "=f"(lo), "=f"(hi) : "l"(p));
}
__device__ __forceinline__ void fma2(uint64_t& acc, uint64_t a, uint64_t b) {
    asm("fma.rn.f32x2 %0, %1, %2, %0;" : "+l"(acc) : "l"(a), "l"(b));
}

// ---------- K1: Wh (node-major), f1, f2 ----------
__global__ void k1_prep(const float* __restrict__ xv,
                        const float* __restrict__ Wheads,
                        const float* __restrict__ a1,
                        const float* __restrict__ a2) {
    __shared__ float sW[HH*FIN*DH];
    __shared__ float sa1[HH*DH], sa2[HH*DH];
    int tid = threadIdx.x;
    for (int t = tid; t < HH*FIN*DH; t += 128) sW[t] = Wheads[t];
    if (tid < HH*DH) { sa1[tid] = a1[tid]; sa2[tid] = a2[tid]; }
    __syncthreads();
    int gn = blockIdx.x * 128 + tid;          // b*N + n
    float x[FIN];
    const float4* xp = (const float4*)(xv + (size_t)gn * FIN);
    #pragma unroll
    for (int i = 0; i < 4; i++) {
        float4 v = xp[i];
        x[i*4+0] = v.x; x[i*4+1] = v.y; x[i*4+2] = v.z; x[i*4+3] = v.w;
    }
    float* whp = g_Wh2 + (size_t)gn * 64;
    #pragma unroll
    for (int h = 0; h < HH; h++) {
        float wh[DH];
        #pragma unroll
        for (int d = 0; d < DH; d++) {
            float s = 0.f;
            #pragma unroll
            for (int f = 0; f < FIN; f++)
                s += x[f] * sW[(h*FIN + f)*DH + d];
            wh[d] = s;
        }
        float f1v = 0.f, f2v = 0.f;
        #pragma unroll
        for (int d = 0; d < DH; d++) { f1v += wh[d]*sa1[h*DH+d]; f2v += wh[d]*sa2[h*DH+d]; }
        ((float4*)(whp + h*8))[0] = make_float4(wh[0], wh[1], wh[2], wh[3]);
        ((float4*)(whp + h*8))[1] = make_float4(wh[4], wh[5], wh[6], wh[7]);
        g_f1v[(size_t)gn*HH + h] = f1v;
        g_f2v[(size_t)gn*HH + h] = f2v;
    }
}

// ---------- K2: warp-per-row, single-pass 8-head attention ----------
__global__ void k2_gat(const float* __restrict__ adj,
                       const float* __restrict__ Wout,
                       const float* __restrict__ a1o,
                       const float* __restrict__ a2o) {
    __shared__ unsigned short ej[8][NN];
    __shared__ float wsm[8][EMAX*HH];
    __shared__ float hcsm[8][64];
    int wid = threadIdx.x >> 5, lane = threadIdx.x & 31;
    int bi = blockIdx.x * 8 + wid;             // b*N + i
    int b = bi >> 9;

    // deterministic ordered edge compaction (ballot)
    const float* arow = adj + (size_t)bi * NN;
    int cnt = 0;
    #pragma unroll 4
    for (int t0 = 0; t0 < NN; t0 += 32) {
        float v = arow[t0 + lane];
        unsigned m = __ballot_sync(FULLM, v > 0.f);
        if (v > 0.f) ej[wid][cnt + __popc(m & ((1u << lane) - 1u))] = (unsigned short)(t0 + lane);
        cnt += __popc(m);
    }
    if (lane == 0) g_cnt[bi] = cnt;
    __syncwarp();
    for (int t = lane; t < cnt; t += 32) g_edges[(size_t)bi*NN + t] = ej[wid][t];

    const float* f2p = g_f2v + (size_t)b*NN*HH;
    const float* whb = g_Wh2 + (size_t)b*NN*64;

    if (cnt > 0 && cnt <= EMAX) {
        // ---- fast path: all 8 heads at once, lane-per-edge ----
        float4 f1a = *(const float4*)(g_f1v + (size_t)bi*HH);
        float4 f1b = *(const float4*)(g_f1v + (size_t)bi*HH + 4);
        float f1r[8] = {f1a.x, f1a.y, f1a.z, f1a.w, f1b.x, f1b.y, f1b.z, f1b.w};
        int ns = (cnt + 31) >> 5;
        float sc[4][8];
        #pragma unroll
        for (int s = 0; s < 4; s++) {
            if (s < ns) {
                int k = s*32 + lane;
                bool act = k < cnt;
                int j = act ? ej[wid][k] : ej[wid][0];
                float4 u = *(const float4*)(f2p + j*8);
                float4 v = *(const float4*)(f2p + j*8 + 4);
                float t8[8] = {u.x,u.y,u.z,u.w,v.x,v.y,v.z,v.w};
                #pragma unroll
                for (int h = 0; h < 8; h++) {
                    float s2 = f1r[h] + t8[h];
                    s2 = (s2 > 0.f) ? s2 : ALPHAC * s2;
                    sc[s][h] = act ? s2 : -3.4e38f;
                }
            } else {
                #pragma unroll
                for (int h = 0; h < 8; h++) sc[s][h] = -3.4e38f;
            }
        }
        float mx[8];
        #pragma unroll
        for (int h = 0; h < 8; h++) mx[h] = sc[0][h];
        #pragma unroll
        for (int s = 1; s < 4; s++) {
            #pragma unroll
            for (int h = 0; h < 8; h++) mx[h] = fmaxf(mx[h], sc[s][h]);
        }
        #pragma unroll
        for (int o = 16; o; o >>= 1) {
            #pragma unroll
            for (int h = 0; h < 8; h++) mx[h] = fmaxf(mx[h], __shfl_xor_sync(FULLM, mx[h], o));
        }
        float sm[8] = {0,0,0,0,0,0,0,0};
        #pragma unroll
        for (int s = 0; s < 4; s++) {
            if (s < ns) {
                #pragma unroll
                for (int h = 0; h < 8; h++) {
                    float w = __expf(sc[s][h] - mx[h]);
                    sc[s][h] = w;
                    sm[h] += w;
                }
            }
        }
        #pragma unroll
        for (int o = 16; o; o >>= 1) {
            #pragma unroll
            for (int h = 0; h < 8; h++) sm[h] += __shfl_xor_sync(FULLM, sm[h], o);
        }
        float inv[8];
        #pragma unroll
        for (int h = 0; h < 8; h++) inv[h] = 1.0f / sm[h];
        #pragma unroll
        for (int s = 0; s < 4; s++) {
            if (s < ns) {
                int k = s*32 + lane;
                if (k < cnt) {
                    #pragma unroll
                    for (int h = 0; h < 8; h++) wsm[wid][k*8 + h] = sc[s][h] * inv[h];
                }
            }
        }
        __syncwarp();
        int h = lane >> 2;
        float acc0 = 0.f, acc1 = 0.f;
        #pragma unroll 8
        for (int k = 0; k < cnt; k++) {
            int j = ej[wid][k];
            float w = wsm[wid][k*8 + h];
            float2 wv = *(const float2*)(whb + (size_t)j*64 + 2*lane);
            acc0 += w * wv.x; acc1 += w * wv.y;
        }
        acc0 = (acc0 > 0.f) ? acc0 : (__expf(acc0) - 1.f);
        acc1 = (acc1 > 0.f) ? acc1 : (__expf(acc1) - 1.f);
        hcsm[wid][2*lane]   = acc0;
        hcsm[wid][2*lane+1] = acc1;
    } else if (cnt == 0) {
        float acc0 = 0.f, acc1 = 0.f;
        #pragma unroll 8
        for (int j = 0; j < NN; j++) {
            float2 wv = *(const float2*)(whb + (size_t)j*64 + 2*lane);
            acc0 += wv.x; acc1 += wv.y;
        }
        acc0 *= (1.0f/NN); acc1 *= (1.0f/NN);
        acc0 = (acc0 > 0.f) ? acc0 : (__expf(acc0) - 1.f);
        acc1 = (acc1 > 0.f) ? acc1 : (__expf(acc1) - 1.f);
        hcsm[wid][2*lane]   = acc0;
        hcsm[wid][2*lane+1] = acc1;
    } else {
        float* wf = &wsm[wid][0];
        for (int h = 0; h < HH; h++) {
            float f1v = g_f1v[(size_t)bi*HH + h];
            float lm = -3.4e38f;
            for (int t = lane; t < cnt; t += 32) {
                float s = f1v + f2p[(size_t)ej[wid][t]*HH + h];
                s = (s > 0.f) ? s : ALPHAC * s;
                wf[t] = s;
                lm = fmaxf(lm, s);
            }
            #pragma unroll
            for (int o = 16; o; o >>= 1) lm = fmaxf(lm, __shfl_xor_sync(FULLM, lm, o));
            float ls = 0.f;
            for (int t = lane; t < cnt; t += 32) {
                float w = __expf(wf[t] - lm);
                wf[t] = w;
                ls += w;
            }
            #pragma unroll
            for (int o = 16; o; o >>= 1) ls += __shfl_xor_sync(FULLM, ls, o);
            __syncwarp();
            int d = lane & 7, ks = lane >> 3;
            float acc = 0.f;
            for (int k = ks; k < cnt; k += 4)
                acc += wf[k] * whb[(size_t)ej[wid][k]*64 + h*8 + d];
            acc += __shfl_down_sync(FULLM, acc, 16);
            acc += __shfl_down_sync(FULLM, acc, 8);
            if (lane < 8) {
                float v = acc / ls;
                hcsm[wid][h*8 + lane] = (v > 0.f) ? v : (__expf(v) - 1.f);
            }
            __syncwarp();
        }
    }
    __syncwarp();
    float s = 0.f;
    #pragma unroll
    for (int f = 0; f < HH*DH; f++) s += hcsm[wid][f] * Wout[f*DO + lane];
    g_Who[(size_t)bi*DO + lane] = s;
    float p1 = s * a1o[lane], p2 = s * a2o[lane];
    #pragma unroll
    for (int o = 16; o; o >>= 1) {
        p1 += __shfl_xor_sync(FULLM, p1, o);
        p2 += __shfl_xor_sync(FULLM, p2, o);
    }
    if (lane == 0) { g_g1[bi] = p1; g_g2[bi] = p2; }
}

// ---------- K3: warp-per-row output attention (lane = output dim) ----------
__global__ void k3_out() {
    __shared__ unsigned short ej[8][NN];
    __shared__ float wbuf[8][NN];
    int wid = threadIdx.x >> 5, lane = threadIdx.x & 31;
    int bi = blockIdx.x * 8 + wid;
    int b = bi >> 9;
    int cnt = g_cnt[bi];
    for (int t = lane; t < cnt; t += 32) ej[wid][t] = g_edges[(size_t)bi*NN + t];
    bool uni = (cnt == 0);
    int M = uni ? NN : cnt;
    float den;
    __syncwarp();
    if (!uni) {
        float g1v = g_g1[bi];
        const float* g2p = g_g2 + b*NN;
        float lm = -3.4e38f;
        for (int t = lane; t < cnt; t += 32) {
            float s = g1v + g2p[ej[wid][t]];
            s = (s > 0.f) ? s : ALPHAC * s;
            wbuf[wid][t] = s;
            lm = fmaxf(lm, s);
        }
        #pragma unroll
        for (int o = 16; o; o >>= 1) lm = fmaxf(lm, __shfl_xor_sync(FULLM, lm, o));
        float ls = 0.f;
        for (int t = lane; t < cnt; t += 32) {
            float w = __expf(wbuf[wid][t] - lm);
            wbuf[wid][t] = w;
            ls += w;
        }
        #pragma unroll
        for (int o = 16; o; o >>= 1) ls += __shfl_xor_sync(FULLM, ls, o);
        den = ls;
        __syncwarp();
    } else {
        den = (float)NN;
    }
    float acc = 0.f;
    const float* whop = g_Who + (size_t)b*NN*DO;
    #pragma unroll 8
    for (int k = 0; k < M; k++) {
        int j = uni ? k : ej[wid][k];
        float w = uni ? 1.f : wbuf[wid][k];
        acc += w * whop[j*DO + lane];
    }
    float v = acc / den;
    g_out[(size_t)bi*DO + lane] = (v > 0.f) ? v : (__expf(v) - 1.f);
}

// ---------- K4: split-K GEMM with packed f32x2 FMA ----------
// grid: NSPLIT(2) n-tiles x KSPLIT(256) k-splits = 512 blocks, 256 threads.
// thread: 4 consecutive n (LDG.128 of W), 8 b as 4 f32x2 pairs (LDS.64 broadcast).
__global__ void __launch_bounds__(256) k4_gemm(const float* __restrict__ Wq) {
    __shared__ __align__(16) float a_s[64][36];   // [kk][b], row 144B (8B-aligned)
    int tid = threadIdx.x;
    int nt  = blockIdx.x & (NSPLIT - 1);
    int ksp = blockIdx.x >> 1;
    int n0 = nt * 256, k0 = ksp * 64;
    int nl = tid & 63;                   // 64 n-slots x 4 cols
    int bg = tid >> 6;                   // 4 groups of 8 b (warp-uniform)

    // stage A: 64 k-rows x 32 b
    for (int idx = tid; idx < 2048; idx += 256) {
        int bb = idx >> 6, kk = idx & 63;
        a_s[kk][bb] = g_out[(size_t)bb*(NN*DO) + k0 + kk];
    }
    __syncthreads();

    uint64_t acc[4][4];                  // [nsub][bpair]
    #pragma unroll
    for (int i = 0; i < 4; i++)
        #pragma unroll
        for (int j = 0; j < 4; j++) acc[i][j] = packf2(0.f, 0.f);

    const float* wqp = Wq + (size_t)k0 * NN + n0 + nl*4;
    #pragma unroll 4
    for (int kk = 0; kk < 64; kk++) {
        float4 w4 = *(const float4*)(wqp + (size_t)kk * NN);   // LDG.128
        const uint64_t* ap = (const uint64_t*)&a_s[kk][bg*8];  // LDS.64 broadcast
        uint64_t a0 = ap[0], a1 = ap[1], a2 = ap[2], a3 = ap[3];
        uint64_t w0 = packf2(w4.x, w4.x), w1 = packf2(w4.y, w4.y);
        uint64_t w2 = packf2(w4.z, w4.z), w3 = packf2(w4.w, w4.w);
        fma2(acc[0][0], a0, w0); fma2(acc[0][1], a1, w0); fma2(acc[0][2], a2, w0); fma2(acc[0][3], a3, w0);
        fma2(acc[1][0], a0, w1); fma2(acc[1][1], a1, w1); fma2(acc[1][2], a2, w1); fma2(acc[1][3], a3, w1);
        fma2(acc[2][0], a0, w2); fma2(acc[2][1], a1, w2); fma2(acc[2][2], a2, w2); fma2(acc[2][3], a3, w2);
        fma2(acc[3][0], a0, w3); fma2(acc[3][1], a1, w3); fma2(acc[3][2], a2, w3); fma2(acc[3][3], a3, w3);
    }

    // epilogue: per b, assemble float4 over the 4 n's
    float* dst = g_part + (size_t)ksp * (BB*NN);
    #pragma unroll
    for (int bp = 0; bp < 4; bp++) {
        float lo0, hi0, lo1, hi1, lo2, hi2, lo3, hi3;
        unpackf2(lo0, hi0, acc[0][bp]);
        unpackf2(lo1, hi1, acc[1][bp]);
        unpackf2(lo2, hi2, acc[2][bp]);
        unpackf2(lo3, hi3, acc[3][bp]);
        int b0 = bg*8 + bp*2;
        *(float4*)(dst + (size_t)b0*NN + n0 + nl*4)     = make_float4(lo0, lo1, lo2, lo3);
        *(float4*)(dst + (size_t)(b0+1)*NN + n0 + nl*4) = make_float4(hi0, hi1, hi2, hi3);
    }
}

// ---------- K5: deterministic reduce + bias ----------
__global__ void k5_reduce(const float* __restrict__ bq, float* __restrict__ q) {
    int idx = blockIdx.x * 256 + threadIdx.x;   // 64 blocks x 256 = 16384
    float s = bq[idx & (NN - 1)];
    #pragma unroll 8
    for (int p = 0; p < KSPLIT; p++)
        s += g_part[(size_t)p * (BB*NN) + idx];
    q[idx] = s;
}

extern "C" void kernel_launch(void* const* d_in, const int* in_sizes, int n_in,
                              void* d_out, int out_size) {
    const float* xv     = (const float*)d_in[0];
    const float* adj    = (const float*)d_in[1];
    const float* Wheads = (const float*)d_in[2];
    const float* a1     = (const float*)d_in[3];
    const float* a2     = (const float*)d_in[4];
    const float* Wout   = (const float*)d_in[5];
    const float* a1o    = (const float*)d_in[6];
    const float* a2o    = (const float*)d_in[7];
    const float* Wq     = (const float*)d_in[8];
    const float* bq     = (const float*)d_in[9];
    float* q = (float*)d_out;

    k1_prep<<<128, 128>>>(xv, Wheads, a1, a2);
    k2_gat<<<BB*NN/8, 256>>>(adj, Wout, a1o, a2o);
    k3_out<<<BB*NN/8, 256>>>();
    k4_gemm<<<NSPLIT*KSPLIT, 256>>>(Wq);
    k5_reduce<<<64, 256>>>(bq, q);
}

// round 7
// speedup vs baseline: 1.1373x; 1.1373x over previous
#include <cuda_runtime.h>
#include <cstdint>

#define BB 32
#define NN 512
#define HH 8
#define DH 8
#define DO 32
#define FIN 16
#define ALPHAC 0.2f
#define FULLM 0xffffffffu
#define EMAX 128          // fast-path edge cap (P(cnt>128) ~ 0; fallback is correct)
#define KSPLIT 256        // k4: 256 splits x 64 k-rows
#define K4KT 64           // k-tile rows per block
#define K4NT 4            // n-tiles of 128 cols

// ---------- scratch (static device globals; no allocation) ----------
__device__ __align__(16) float g_Wh2[BB*NN*64];   // 8 MB  [b][n][h*8+d]
__device__ __align__(16) float g_f1v[BB*NN*HH];
__device__ __align__(16) float g_f2v[BB*NN*HH];
__device__ unsigned short g_edges[(size_t)BB*NN*NN];
__device__ int   g_cnt[BB*NN];
__device__ __align__(16) float g_Who[BB*NN*DO];
__device__ float g_g1[BB*NN];
__device__ float g_g2[BB*NN];
__device__ __align__(16) float g_out[BB*NN*DO];   // 2 MB == A[32][16384]
__device__ __align__(16) float g_part[(size_t)KSPLIT * BB * NN];  // 16 MB partials

__device__ __forceinline__ uint64_t packf2(float lo, float hi) {
    uint64_t p;
    asm("mov.b64 %0, {%1, %2};" : "=l"(p) : "f"(lo), "f"(hi));
    return p;
}
__device__ __forceinline__ void unpackf2(float& lo, float& hi, uint64_t p) {
    asm("mov.b64 {%0, %1}, %2;" : "=f"(lo), "=f"(hi) : "l"(p));
}
__device__ __forceinline__ void fma2(uint64_t& acc, uint64_t a, uint64_t b) {
    asm("fma.rn.f32x2 %0, %1, %2, %0;" : "+l"(acc) : "l"(a), "l"(b));
}

// ---------- K1: Wh (node-major), f1, f2 ----------
__global__ void k1_prep(const float* __restrict__ xv,
                        const float* __restrict__ Wheads,
                        const float* __restrict__ a1,
                        const float* __restrict__ a2) {
    __shared__ float sW[HH*FIN*DH];
    __shared__ float sa1[HH*DH], sa2[HH*DH];
    int tid = threadIdx.x;
    for (int t = tid; t < HH*FIN*DH; t += 128) sW[t] = Wheads[t];
    if (tid < HH*DH) { sa1[tid] = a1[tid]; sa2[tid] = a2[tid]; }
    __syncthreads();
    int gn = blockIdx.x * 128 + tid;          // b*N + n
    float x[FIN];
    const float4* xp = (const float4*)(xv + (size_t)gn * FIN);
    #pragma unroll
    for (int i = 0; i < 4; i++) {
        float4 v = xp[i];
        x[i*4+0] = v.x; x[i*4+1] = v.y; x[i*4+2] = v.z; x[i*4+3] = v.w;
    }
    float* whp = g_Wh2 + (size_t)gn * 64;
    #pragma unroll
    for (int h = 0; h < HH; h++) {
        float wh[DH];
        #pragma unroll
        for (int d = 0; d < DH; d++) {
            float s = 0.f;
            #pragma unroll
            for (int f = 0; f < FIN; f++)
                s += x[f] * sW[(h*FIN + f)*DH + d];
            wh[d] = s;
        }
        float f1v = 0.f, f2v = 0.f;
        #pragma unroll
        for (int d = 0; d < DH; d++) { f1v += wh[d]*sa1[h*DH+d]; f2v += wh[d]*sa2[h*DH+d]; }
        ((float4*)(whp + h*8))[0] = make_float4(wh[0], wh[1], wh[2], wh[3]);
        ((float4*)(whp + h*8))[1] = make_float4(wh[4], wh[5], wh[6], wh[7]);
        g_f1v[(size_t)gn*HH + h] = f1v;
        g_f2v[(size_t)gn*HH + h] = f2v;
    }
}

// ---------- K2: warp-per-row, single-pass 8-head attention ----------
__global__ void k2_gat(const float* __restrict__ adj,
                       const float* __restrict__ Wout,
                       const float* __restrict__ a1o,
                       const float* __restrict__ a2o) {
    __shared__ unsigned short ej[8][NN];
    __shared__ float wsm[8][EMAX*HH];
    __shared__ float hcsm[8][64];
    int wid = threadIdx.x >> 5, lane = threadIdx.x & 31;
    int bi = blockIdx.x * 8 + wid;             // b*N + i
    int b = bi >> 9;

    // deterministic ordered edge compaction (ballot)
    const float* arow = adj + (size_t)bi * NN;
    int cnt = 0;
    #pragma unroll 4
    for (int t0 = 0; t0 < NN; t0 += 32) {
        float v = arow[t0 + lane];
        unsigned m = __ballot_sync(FULLM, v > 0.f);
        if (v > 0.f) ej[wid][cnt + __popc(m & ((1u << lane) - 1u))] = (unsigned short)(t0 + lane);
        cnt += __popc(m);
    }
    if (lane == 0) g_cnt[bi] = cnt;
    __syncwarp();
    for (int t = lane; t < cnt; t += 32) g_edges[(size_t)bi*NN + t] = ej[wid][t];

    const float* f2p = g_f2v + (size_t)b*NN*HH;
    const float* whb = g_Wh2 + (size_t)b*NN*64;

    if (cnt > 0 && cnt <= EMAX) {
        // ---- fast path: all 8 heads at once, lane-per-edge ----
        float4 f1a = *(const float4*)(g_f1v + (size_t)bi*HH);
        float4 f1b = *(const float4*)(g_f1v + (size_t)bi*HH + 4);
        float f1r[8] = {f1a.x, f1a.y, f1a.z, f1a.w, f1b.x, f1b.y, f1b.z, f1b.w};
        int ns = (cnt + 31) >> 5;
        float sc[4][8];
        #pragma unroll
        for (int s = 0; s < 4; s++) {
            if (s < ns) {
                int k = s*32 + lane;
                bool act = k < cnt;
                int j = act ? ej[wid][k] : ej[wid][0];
                float4 u = *(const float4*)(f2p + j*8);
                float4 v = *(const float4*)(f2p + j*8 + 4);
                float t8[8] = {u.x,u.y,u.z,u.w,v.x,v.y,v.z,v.w};
                #pragma unroll
                for (int h = 0; h < 8; h++) {
                    float s2 = f1r[h] + t8[h];
                    s2 = (s2 > 0.f) ? s2 : ALPHAC * s2;
                    sc[s][h] = act ? s2 : -3.4e38f;
                }
            } else {
                #pragma unroll
                for (int h = 0; h < 8; h++) sc[s][h] = -3.4e38f;
            }
        }
        float mx[8];
        #pragma unroll
        for (int h = 0; h < 8; h++) mx[h] = sc[0][h];
        #pragma unroll
        for (int s = 1; s < 4; s++) {
            #pragma unroll
            for (int h = 0; h < 8; h++) mx[h] = fmaxf(mx[h], sc[s][h]);
        }
        #pragma unroll
        for (int o = 16; o; o >>= 1) {
            #pragma unroll
            for (int h = 0; h < 8; h++) mx[h] = fmaxf(mx[h], __shfl_xor_sync(FULLM, mx[h], o));
        }
        float sm[8] = {0,0,0,0,0,0,0,0};
        #pragma unroll
        for (int s = 0; s < 4; s++) {
            if (s < ns) {
                #pragma unroll
                for (int h = 0; h < 8; h++) {
                    float w = __expf(sc[s][h] - mx[h]);
                    sc[s][h] = w;
                    sm[h] += w;
                }
            }
        }
        #pragma unroll
        for (int o = 16; o; o >>= 1) {
            #pragma unroll
            for (int h = 0; h < 8; h++) sm[h] += __shfl_xor_sync(FULLM, sm[h], o);
        }
        float inv[8];
        #pragma unroll
        for (int h = 0; h < 8; h++) inv[h] = 1.0f / sm[h];
        #pragma unroll
        for (int s = 0; s < 4; s++) {
            if (s < ns) {
                int k = s*32 + lane;
                if (k < cnt) {
                    #pragma unroll
                    for (int h = 0; h < 8; h++) wsm[wid][k*8 + h] = sc[s][h] * inv[h];
                }
            }
        }
        __syncwarp();
        int h = lane >> 2;
        float acc0 = 0.f, acc1 = 0.f;
        #pragma unroll 4
        for (int k = 0; k < cnt; k++) {
            int j = ej[wid][k];
            float w = wsm[wid][k*8 + h];
            float2 wv = *(const float2*)(whb + (size_t)j*64 + 2*lane);
            acc0 += w * wv.x; acc1 += w * wv.y;
        }
        acc0 = (acc0 > 0.f) ? acc0 : (__expf(acc0) - 1.f);
        acc1 = (acc1 > 0.f) ? acc1 : (__expf(acc1) - 1.f);
        hcsm[wid][2*lane]   = acc0;
        hcsm[wid][2*lane+1] = acc1;
    } else if (cnt == 0) {
        float acc0 = 0.f, acc1 = 0.f;
        #pragma unroll 4
        for (int j = 0; j < NN; j++) {
            float2 wv = *(const float2*)(whb + (size_t)j*64 + 2*lane);
            acc0 += wv.x; acc1 += wv.y;
        }
        acc0 *= (1.0f/NN); acc1 *= (1.0f/NN);
        acc0 = (acc0 > 0.f) ? acc0 : (__expf(acc0) - 1.f);
        acc1 = (acc1 > 0.f) ? acc1 : (__expf(acc1) - 1.f);
        hcsm[wid][2*lane]   = acc0;
        hcsm[wid][2*lane+1] = acc1;
    } else {
        float* wf = &wsm[wid][0];
        for (int h = 0; h < HH; h++) {
            float f1v = g_f1v[(size_t)bi*HH + h];
            float lm = -3.4e38f;
            for (int t = lane; t < cnt; t += 32) {
                float s = f1v + f2p[(size_t)ej[wid][t]*HH + h];
                s = (s > 0.f) ? s : ALPHAC * s;
                wf[t] = s;
                lm = fmaxf(lm, s);
            }
            #pragma unroll
            for (int o = 16; o; o >>= 1) lm = fmaxf(lm, __shfl_xor_sync(FULLM, lm, o));
            float ls = 0.f;
            for (int t = lane; t < cnt; t += 32) {
                float w = __expf(wf[t] - lm);
                wf[t] = w;
                ls += w;
            }
            #pragma unroll
            for (int o = 16; o; o >>= 1) ls += __shfl_xor_sync(FULLM, ls, o);
            __syncwarp();
            int d = lane & 7, ks = lane >> 3;
            float acc = 0.f;
            for (int k = ks; k < cnt; k += 4)
                acc += wf[k] * whb[(size_t)ej[wid][k]*64 + h*8 + d];
            acc += __shfl_down_sync(FULLM, acc, 16);
            acc += __shfl_down_sync(FULLM, acc, 8);
            if (lane < 8) {
                float v = acc / ls;
                hcsm[wid][h*8 + lane] = (v > 0.f) ? v : (__expf(v) - 1.f);
            }
            __syncwarp();
        }
    }
    __syncwarp();
    float s = 0.f;
    #pragma unroll
    for (int f = 0; f < HH*DH; f++) s += hcsm[wid][f] * Wout[f*DO + lane];
    g_Who[(size_t)bi*DO + lane] = s;
    float p1 = s * a1o[lane], p2 = s * a2o[lane];
    #pragma unroll
    for (int o = 16; o; o >>= 1) {
        p1 += __shfl_xor_sync(FULLM, p1, o);
        p2 += __shfl_xor_sync(FULLM, p2, o);
    }
    if (lane == 0) { g_g1[bi] = p1; g_g2[bi] = p2; }
}

// ---------- K3: warp-per-row output attention (lane = output dim) ----------
__global__ void k3_out() {
    __shared__ unsigned short ej[8][NN];
    __shared__ float wbuf[8][NN];
    int wid = threadIdx.x >> 5, lane = threadIdx.x & 31;
    int bi = blockIdx.x * 8 + wid;
    int b = bi >> 9;
    int cnt = g_cnt[bi];
    for (int t = lane; t < cnt; t += 32) ej[wid][t] = g_edges[(size_t)bi*NN + t];
    bool uni = (cnt == 0);
    int M = uni ? NN : cnt;
    float den;
    __syncwarp();
    if (!uni) {
        float g1v = g_g1[bi];
        const float* g2p = g_g2 + b*NN;
        float lm = -3.4e38f;
        for (int t = lane; t < cnt; t += 32) {
            float s = g1v + g2p[ej[wid][t]];
            s = (s > 0.f) ? s : ALPHAC * s;
            wbuf[wid][t] = s;
            lm = fmaxf(lm, s);
        }
        #pragma unroll
        for (int o = 16; o; o >>= 1) lm = fmaxf(lm, __shfl_xor_sync(FULLM, lm, o));
        float ls = 0.f;
        for (int t = lane; t < cnt; t += 32) {
            float w = __expf(wbuf[wid][t] - lm);
            wbuf[wid][t] = w;
            ls += w;
        }
        #pragma unroll
        for (int o = 16; o; o >>= 1) ls += __shfl_xor_sync(FULLM, ls, o);
        den = ls;
        __syncwarp();
    } else {
        den = (float)NN;
    }
    float acc = 0.f;
    const float* whop = g_Who + (size_t)b*NN*DO;
    #pragma unroll 4
    for (int k = 0; k < M; k++) {
        int j = uni ? k : ej[wid][k];
        float w = uni ? 1.f : wbuf[wid][k];
        acc += w * whop[j*DO + lane];
    }
    float v = acc / den;
    g_out[(size_t)bi*DO + lane] = (v > 0.f) ? v : (__expf(v) - 1.f);
}

// ---------- K4: smem-staged split-K GEMM, f32x2 FMA ----------
// grid = K4NT(4 n-tiles of 128) x KSPLIT(256, 64 k-rows each) = 1024 blocks, 256 thr
// thread: 2 consecutive n (LDS.64 W) x 8 b (4 f32x2 pairs, LDS.64 broadcast A)
__global__ void __launch_bounds__(256) k4_gemm(const float* __restrict__ Wq) {
    __shared__ __align__(16) float sW[K4KT][128];    // 32 KB
    __shared__ __align__(16) float sA[K4KT][34];     // 8.5 KB (row 136B, 8B-aligned)
    int tid = threadIdx.x;
    int nt  = blockIdx.x & (K4NT - 1);
    int ksp = blockIdx.x >> 2;
    int n0 = nt * 128, k0 = ksp * K4KT;

    // stage W: 64 rows x 128 floats = 2048 float4, 8 per thread (independent)
    #pragma unroll
    for (int p = 0; p < 8; p++) {
        int idx = tid + p * 256;
        int row = idx >> 5, col = idx & 31;
        float4 v = *(const float4*)(Wq + (size_t)(k0 + row) * NN + n0 + col*4);
        *(float4*)&sW[row][col*4] = v;
    }
    // stage A: 32 b x 64 k = 512 float4 reads, transposed to [kk][bb]
    #pragma unroll
    for (int p = 0; p < 2; p++) {
        int idx = tid + p * 256;
        int bb = idx >> 4, kq = idx & 15;
        float4 v = *(const float4*)(g_out + (size_t)bb * (NN*DO) + k0 + kq*4);
        sA[kq*4+0][bb] = v.x; sA[kq*4+1][bb] = v.y;
        sA[kq*4+2][bb] = v.z; sA[kq*4+3][bb] = v.w;
    }
    __syncthreads();

    int nl = tid & 63;          // n-pair index: cols n0 + nl*2, +1
    int bg = tid >> 6;          // b-group of 8 (warp-uniform)
    uint64_t acc[2][4];
    #pragma unroll
    for (int i = 0; i < 2; i++)
        #pragma unroll
        for (int j = 0; j < 4; j++) acc[i][j] = packf2(0.f, 0.f);

    #pragma unroll 8
    for (int kk = 0; kk < K4KT; kk++) {
        float2 w2 = *(const float2*)&sW[kk][nl*2];            // LDS.64, conflict-free
        const uint64_t* ap = (const uint64_t*)&sA[kk][bg*8];  // LDS.64 broadcast
        uint64_t a0 = ap[0], a1 = ap[1], a2 = ap[2], a3 = ap[3];
        uint64_t wa = packf2(w2.x, w2.x);
        uint64_t wb = packf2(w2.y, w2.y);
        fma2(acc[0][0], a0, wa); fma2(acc[0][1], a1, wa);
        fma2(acc[0][2], a2, wa); fma2(acc[0][3], a3, wa);
        fma2(acc[1][0], a0, wb); fma2(acc[1][1], a1, wb);
        fma2(acc[1][2], a2, wb); fma2(acc[1][3], a3, wb);
    }

    // epilogue: per b, float2 over the 2 n's (coalesced across nl)
    float* dst = g_part + (size_t)ksp * (BB*NN) + n0 + nl*2;
    #pragma unroll
    for (int bp = 0; bp < 4; bp++) {
        float l0, h0, l1, h1;
        unpackf2(l0, h0, acc[0][bp]);   // n+0 for (b_lo, b_hi)
        unpackf2(l1, h1, acc[1][bp]);   // n+1 for (b_lo, b_hi)
        int b0 = bg*8 + bp*2;
        *(float2*)(dst + (size_t)b0*NN)     = make_float2(l0, l1);
        *(float2*)(dst + (size_t)(b0+1)*NN) = make_float2(h0, h1);
    }
}

// ---------- K5: deterministic reduce + bias ----------
__global__ void k5_reduce(const float* __restrict__ bq, float* __restrict__ q) {
    int idx = blockIdx.x * 256 + threadIdx.x;   // 64 blocks x 256 = 16384
    float s = bq[idx & (NN - 1)];
    #pragma unroll 16
    for (int p = 0; p < KSPLIT; p++)
        s += g_part[(size_t)p * (BB*NN) + idx];
    q[idx] = s;
}

extern "C" void kernel_launch(void* const* d_in, const int* in_sizes, int n_in,
                              void* d_out, int out_size) {
    const float* xv     = (const float*)d_in[0];
    const float* adj    = (const float*)d_in[1];
    const float* Wheads = (const float*)d_in[2];
    const float* a1     = (const float*)d_in[3];
    const float* a2     = (const float*)d_in[4];
    const float* Wout   = (const float*)d_in[5];
    const float* a1o    = (const float*)d_in[6];
    const float* a2o    = (const float*)d_in[7];
    const float* Wq     = (const float*)d_in[8];
    const float* bq     = (const float*)d_in[9];
    float* q = (float*)d_out;

    k1_prep<<<128, 128>>>(xv, Wheads, a1, a2);
    k2_gat<<<BB*NN/8, 256>>>(adj, Wout, a1o, a2o);
    k3_out<<<BB*NN/8, 256>>>();
    k4_gemm<<<K4NT*KSPLIT, 256>>>(Wq);
    k5_reduce<<<64, 256>>>(bq, q);
}

// round 8
// speedup vs baseline: 1.2146x; 1.0680x over previous
#include <cuda_runtime.h>
#include <cstdint>

#define BB 32
#define NN 512
#define HH 8
#define DH 8
#define DO 32
#define FIN 16
#define ALPHAC 0.2f
#define FULLM 0xffffffffu
#define EMAX 128          // fast-path edge cap (P(cnt>128) ~ 0; fallback is correct)
#define KSPLIT 128        // k4: 128 splits x (2 stages x 64 k-rows)
#define K4NT 4            // n-tiles of 128 cols
#define PREF 512          // k2 prefetch blocks: 512 x 64KiB = 32MiB = all of Wq

// ---------- scratch (static device globals; no allocation) ----------
__device__ __align__(16) float g_Wh2[BB*NN*64];   // 8 MB  [b][n][h*8+d]
__device__ __align__(16) float g_f1v[BB*NN*HH];
__device__ __align__(16) float g_f2v[BB*NN*HH];
__device__ unsigned short g_edges[(size_t)BB*NN*NN];
__device__ int   g_cnt[BB*NN];
__device__ __align__(16) float g_Who[BB*NN*DO];
__device__ float g_g1[BB*NN];
__device__ float g_g2[BB*NN];
__device__ __align__(16) float g_out[BB*NN*DO];   // 2 MB == A[32][16384]
__device__ __align__(16) float g_part[(size_t)KSPLIT * BB * NN];  // 8 MB partials
__device__ float g_dummy[PREF*256];               // prefetch sink

__device__ __forceinline__ uint64_t packf2(float lo, float hi) {
    uint64_t p;
    asm("mov.b64 %0, {%1, %2};" : "=l"(p) : "f"(lo), "f"(hi));
    return p;
}
__device__ __forceinline__ void unpackf2(float& lo, float& hi, uint64_t p) {
    asm("mov.b64 {%0, %1}, %2;" : "=f"(lo), "=f"(hi) : "l"(p));
}
__device__ __forceinline__ void fma2(uint64_t& acc, uint64_t a, uint64_t b) {
    asm("fma.rn.f32x2 %0, %1, %2, %0;" : "+l"(acc) : "l"(a), "l"(b));
}

// ---------- K1: Wh (node-major), f1, f2 ----------
__global__ void k1_prep(const float* __restrict__ xv,
                        const float* __restrict__ Wheads,
                        const float* __restrict__ a1,
                        const float* __restrict__ a2) {
    __shared__ float sW[HH*FIN*DH];
    __shared__ float sa1[HH*DH], sa2[HH*DH];
    int tid = threadIdx.x;
    for (int t = tid; t < HH*FIN*DH; t += 128) sW[t] = Wheads[t];
    if (tid < HH*DH) { sa1[tid] = a1[tid]; sa2[tid] = a2[tid]; }
    __syncthreads();
    int gn = blockIdx.x * 128 + tid;          // b*N + n
    float x[FIN];
    const float4* xp = (const float4*)(xv + (size_t)gn * FIN);
    #pragma unroll
    for (int i = 0; i < 4; i++) {
        float4 v = xp[i];
        x[i*4+0] = v.x; x[i*4+1] = v.y; x[i*4+2] = v.z; x[i*4+3] = v.w;
    }
    float* whp = g_Wh2 + (size_t)gn * 64;
    #pragma unroll
    for (int h = 0; h < HH; h++) {
        float wh[DH];
        #pragma unroll
        for (int d = 0; d < DH; d++) {
            float s = 0.f;
            #pragma unroll
            for (int f = 0; f < FIN; f++)
                s += x[f] * sW[(h*FIN + f)*DH + d];
            wh[d] = s;
        }
        float f1v = 0.f, f2v = 0.f;
        #pragma unroll
        for (int d = 0; d < DH; d++) { f1v += wh[d]*sa1[h*DH+d]; f2v += wh[d]*sa2[h*DH+d]; }
        ((float4*)(whp + h*8))[0] = make_float4(wh[0], wh[1], wh[2], wh[3]);
        ((float4*)(whp + h*8))[1] = make_float4(wh[4], wh[5], wh[6], wh[7]);
        g_f1v[(size_t)gn*HH + h] = f1v;
        g_f2v[(size_t)gn*HH + h] = f2v;
    }
}

// ---------- K2: Wq L2-prefetch (first PREF blocks) + warp-per-row attention ----------
__global__ void k2_gat(const float* __restrict__ adj,
                       const float* __restrict__ Wout,
                       const float* __restrict__ a1o,
                       const float* __restrict__ a2o,
                       const float* __restrict__ Wq) {
    __shared__ unsigned short ej[8][NN];
    __shared__ float wsm[8][EMAX*HH];
    __shared__ float hcsm[8][64];
    int wid = threadIdx.x >> 5, lane = threadIdx.x & 31;

    if (blockIdx.x < PREF) {
        // stream 64KiB of Wq into L2 (evict-normal via __ldcg: L2-only fill)
        const float4* src = (const float4*)(Wq + (size_t)blockIdx.x * 16384);
        float s = 0.f;
        #pragma unroll
        for (int p = 0; p < 16; p++) {
            float4 v = __ldcg(src + threadIdx.x + p * 256);
            s += v.x + v.y + v.z + v.w;
        }
        g_dummy[(blockIdx.x << 8) + threadIdx.x] = s;   // defeat DCE; deterministic
        return;
    }

    int bi = (blockIdx.x - PREF) * 8 + wid;    // b*N + i
    int b = bi >> 9;

    // deterministic ordered edge compaction: float4 + nibble prefix-scan
    const float* arow = adj + (size_t)bi * NN;
    int cnt = 0;
    #pragma unroll
    for (int t0 = 0; t0 < NN; t0 += 128) {
        float4 v = *(const float4*)(arow + t0 + lane*4);
        int nib = (v.x > 0.f) | ((v.y > 0.f) << 1) | ((v.z > 0.f) << 2) | ((v.w > 0.f) << 3);
        int c4 = __popc(nib);
        int incl = c4;
        #pragma unroll
        for (int o = 1; o < 32; o <<= 1) {
            int t = __shfl_up_sync(FULLM, incl, o);
            if (lane >= o) incl += t;
        }
        int base = cnt + (incl - c4);
        int col = t0 + lane*4;
        if (nib & 1) { ej[wid][base] = (unsigned short)(col + 0); base++; }
        if (nib & 2) { ej[wid][base] = (unsigned short)(col + 1); base++; }
        if (nib & 4) { ej[wid][base] = (unsigned short)(col + 2); base++; }
        if (nib & 8) { ej[wid][base] = (unsigned short)(col + 3); base++; }
        cnt += __shfl_sync(FULLM, incl, 31);
    }
    if (lane == 0) g_cnt[bi] = cnt;
    __syncwarp();
    for (int t = lane; t < cnt; t += 32) g_edges[(size_t)bi*NN + t] = ej[wid][t];

    const float* f2p = g_f2v + (size_t)b*NN*HH;
    const float* whb = g_Wh2 + (size_t)b*NN*64;

    if (cnt > 0 && cnt <= EMAX) {
        // ---- fast path: all 8 heads at once, lane-per-edge ----
        float4 f1a = *(const float4*)(g_f1v + (size_t)bi*HH);
        float4 f1b = *(const float4*)(g_f1v + (size_t)bi*HH + 4);
        float f1r[8] = {f1a.x, f1a.y, f1a.z, f1a.w, f1b.x, f1b.y, f1b.z, f1b.w};
        int ns = (cnt + 31) >> 5;
        float sc[4][8];
        #pragma unroll
        for (int s = 0; s < 4; s++) {
            if (s < ns) {
                int k = s*32 + lane;
                bool act = k < cnt;
                int j = act ? ej[wid][k] : ej[wid][0];
                float4 u = *(const float4*)(f2p + j*8);
                float4 v = *(const float4*)(f2p + j*8 + 4);
                float t8[8] = {u.x,u.y,u.z,u.w,v.x,v.y,v.z,v.w};
                #pragma unroll
                for (int h = 0; h < 8; h++) {
                    float s2 = f1r[h] + t8[h];
                    s2 = (s2 > 0.f) ? s2 : ALPHAC * s2;
                    sc[s][h] = act ? s2 : -3.4e38f;
                }
            } else {
                #pragma unroll
                for (int h = 0; h < 8; h++) sc[s][h] = -3.4e38f;
            }
        }
        float mx[8];
        #pragma unroll
        for (int h = 0; h < 8; h++) mx[h] = sc[0][h];
        #pragma unroll
        for (int s = 1; s < 4; s++) {
            #pragma unroll
            for (int h = 0; h < 8; h++) mx[h] = fmaxf(mx[h], sc[s][h]);
        }
        #pragma unroll
        for (int o = 16; o; o >>= 1) {
            #pragma unroll
            for (int h = 0; h < 8; h++) mx[h] = fmaxf(mx[h], __shfl_xor_sync(FULLM, mx[h], o));
        }
        float sm[8] = {0,0,0,0,0,0,0,0};
        #pragma unroll
        for (int s = 0; s < 4; s++) {
            if (s < ns) {
                #pragma unroll
                for (int h = 0; h < 8; h++) {
                    float w = __expf(sc[s][h] - mx[h]);
                    sc[s][h] = w;
                    sm[h] += w;
                }
            }
        }
        #pragma unroll
        for (int o = 16; o; o >>= 1) {
            #pragma unroll
            for (int h = 0; h < 8; h++) sm[h] += __shfl_xor_sync(FULLM, sm[h], o);
        }
        float inv[8];
        #pragma unroll
        for (int h = 0; h < 8; h++) inv[h] = 1.0f / sm[h];
        #pragma unroll
        for (int s = 0; s < 4; s++) {
            if (s < ns) {
                int k = s*32 + lane;
                if (k < cnt) {
                    #pragma unroll
                    for (int h = 0; h < 8; h++) wsm[wid][k*8 + h] = sc[s][h] * inv[h];
                }
            }
        }
        __syncwarp();
        int h = lane >> 2;
        float acc0 = 0.f, acc1 = 0.f;
        #pragma unroll 4
        for (int k = 0; k < cnt; k++) {
            int j = ej[wid][k];
            float w = wsm[wid][k*8 + h];
            float2 wv = *(const float2*)(whb + (size_t)j*64 + 2*lane);
            acc0 += w * wv.x; acc1 += w * wv.y;
        }
        acc0 = (acc0 > 0.f) ? acc0 : (__expf(acc0) - 1.f);
        acc1 = (acc1 > 0.f) ? acc1 : (__expf(acc1) - 1.f);
        hcsm[wid][2*lane]   = acc0;
        hcsm[wid][2*lane+1] = acc1;
    } else if (cnt == 0) {
        float acc0 = 0.f, acc1 = 0.f;
        #pragma unroll 4
        for (int j = 0; j < NN; j++) {
            float2 wv = *(const float2*)(whb + (size_t)j*64 + 2*lane);
            acc0 += wv.x; acc1 += wv.y;
        }
        acc0 *= (1.0f/NN); acc1 *= (1.0f/NN);
        acc0 = (acc0 > 0.f) ? acc0 : (__expf(acc0) - 1.f);
        acc1 = (acc1 > 0.f) ? acc1 : (__expf(acc1) - 1.f);
        hcsm[wid][2*lane]   = acc0;
        hcsm[wid][2*lane+1] = acc1;
    } else {
        float* wf = &wsm[wid][0];
        for (int h = 0; h < HH; h++) {
            float f1v = g_f1v[(size_t)bi*HH + h];
            float lm = -3.4e38f;
            for (int t = lane; t < cnt; t += 32) {
                float s = f1v + f2p[(size_t)ej[wid][t]*HH + h];
                s = (s > 0.f) ? s : ALPHAC * s;
                wf[t] = s;
                lm = fmaxf(lm, s);
            }
            #pragma unroll
            for (int o = 16; o; o >>= 1) lm = fmaxf(lm, __shfl_xor_sync(FULLM, lm, o));
            float ls = 0.f;
            for (int t = lane; t < cnt; t += 32) {
                float w = __expf(wf[t] - lm);
                wf[t] = w;
                ls += w;
            }
            #pragma unroll
            for (int o = 16; o; o >>= 1) ls += __shfl_xor_sync(FULLM, ls, o);
            __syncwarp();
            int d = lane & 7, ks = lane >> 3;
            float acc = 0.f;
            for (int k = ks; k < cnt; k += 4)
                acc += wf[k] * whb[(size_t)ej[wid][k]*64 + h*8 + d];
            acc += __shfl_down_sync(FULLM, acc, 16);
            acc += __shfl_down_sync(FULLM, acc, 8);
            if (lane < 8) {
                float v = acc / ls;
                hcsm[wid][h*8 + lane] = (v > 0.f) ? v : (__expf(v) - 1.f);
            }
            __syncwarp();
        }
    }
    __syncwarp();
    float s = 0.f;
    #pragma unroll
    for (int f = 0; f < HH*DH; f++) s += hcsm[wid][f] * Wout[f*DO + lane];
    g_Who[(size_t)bi*DO + lane] = s;
    float p1 = s * a1o[lane], p2 = s * a2o[lane];
    #pragma unroll
    for (int o = 16; o; o >>= 1) {
        p1 += __shfl_xor_sync(FULLM, p1, o);
        p2 += __shfl_xor_sync(FULLM, p2, o);
    }
    if (lane == 0) { g_g1[bi] = p1; g_g2[bi] = p2; }
}

// ---------- K3: warp-per-row output attention (lane = output dim) ----------
__global__ void k3_out() {
    __shared__ unsigned short ej[8][NN];
    __shared__ float wbuf[8][NN];
    int wid = threadIdx.x >> 5, lane = threadIdx.x & 31;
    int bi = blockIdx.x * 8 + wid;
    int b = bi >> 9;
    int cnt = g_cnt[bi];
    for (int t = lane; t < cnt; t += 32) ej[wid][t] = g_edges[(size_t)bi*NN + t];
    bool uni = (cnt == 0);
    int M = uni ? NN : cnt;
    float den;
    __syncwarp();
    if (!uni) {
        float g1v = g_g1[bi];
        const float* g2p = g_g2 + b*NN;
        float lm = -3.4e38f;
        for (int t = lane; t < cnt; t += 32) {
            float s = g1v + g2p[ej[wid][t]];
            s = (s > 0.f) ? s : ALPHAC * s;
            wbuf[wid][t] = s;
            lm = fmaxf(lm, s);
        }
        #pragma unroll
        for (int o = 16; o; o >>= 1) lm = fmaxf(lm, __shfl_xor_sync(FULLM, lm, o));
        float ls = 0.f;
        for (int t = lane; t < cnt; t += 32) {
            float w = __expf(wbuf[wid][t] - lm);
            wbuf[wid][t] = w;
            ls += w;
        }
        #pragma unroll
        for (int o = 16; o; o >>= 1) ls += __shfl_xor_sync(FULLM, ls, o);
        den = ls;
        __syncwarp();
    } else {
        den = (float)NN;
    }
    float acc = 0.f;
    const float* whop = g_Who + (size_t)b*NN*DO;
    #pragma unroll 4
    for (int k = 0; k < M; k++) {
        int j = uni ? k : ej[wid][k];
        float w = uni ? 1.f : wbuf[wid][k];
        acc += w * whop[j*DO + lane];
    }
    float v = acc / den;
    g_out[(size_t)bi*DO + lane] = (v > 0.f) ? v : (__expf(v) - 1.f);
}

// ---------- K4: smem-staged split-K GEMM, f32x2 FMA, 2 stages x 64 k-rows ----------
// grid = K4NT(4 n-tiles of 128) x KSPLIT(128) = 512 blocks, 256 threads
__global__ void __launch_bounds__(256) k4_gemm(const float* __restrict__ Wq) {
    __shared__ __align__(16) float sW[64][128];      // 32 KB
    __shared__ __align__(16) float sA[64][34];       // 8.5 KB
    int tid = threadIdx.x;
    int nt  = blockIdx.x & (K4NT - 1);
    int ksp = blockIdx.x >> 2;
    int n0 = nt * 128;

    int nl = tid & 63;          // n-pair index: cols n0 + nl*2, +1
    int bg = tid >> 6;          // b-group of 8 (warp-uniform)
    uint64_t acc[2][4];
    #pragma unroll
    for (int i = 0; i < 2; i++)
        #pragma unroll
        for (int j = 0; j < 4; j++) acc[i][j] = packf2(0.f, 0.f);

    #pragma unroll
    for (int st = 0; st < 2; st++) {
        int k0 = ksp * 128 + st * 64;
        if (st) __syncthreads();                     // WAR: finish reads before restage
        // stage W: 64 rows x 128 floats (L2-hot after k2 prefetch)
        #pragma unroll
        for (int p = 0; p < 8; p++) {
            int idx = tid + p * 256;
            int row = idx >> 5, col = idx & 31;
            float4 v = *(const float4*)(Wq + (size_t)(k0 + row) * NN + n0 + col*4);
            *(float4*)&sW[row][col*4] = v;
        }
        // stage A: 32 b x 64 k, transposed to [kk][bb]
        #pragma unroll
        for (int p = 0; p < 2; p++) {
            int idx = tid + p * 256;
            int bb = idx >> 4, kq = idx & 15;
            float4 v = *(const float4*)(g_out + (size_t)bb * (NN*DO) + k0 + kq*4);
            sA[kq*4+0][bb] = v.x; sA[kq*4+1][bb] = v.y;
            sA[kq*4+2][bb] = v.z; sA[kq*4+3][bb] = v.w;
        }
        __syncthreads();

        #pragma unroll 8
        for (int kk = 0; kk < 64; kk++) {
            float2 w2 = *(const float2*)&sW[kk][nl*2];            // LDS.64
            const uint64_t* ap = (const uint64_t*)&sA[kk][bg*8];  // LDS.64 broadcast
            uint64_t a0 = ap[0], a1 = ap[1], a2 = ap[2], a3 = ap[3];
            uint64_t wa = packf2(w2.x, w2.x);
            uint64_t wb = packf2(w2.y, w2.y);
            fma2(acc[0][0], a0, wa); fma2(acc[0][1], a1, wa);
            fma2(acc[0][2], a2, wa); fma2(acc[0][3], a3, wa);
            fma2(acc[1][0], a0, wb); fma2(acc[1][1], a1, wb);
            fma2(acc[1][2], a2, wb); fma2(acc[1][3], a3, wb);
        }
    }

    // epilogue: per b, float2 over the 2 n's (coalesced across nl)
    float* dst = g_part + (size_t)ksp * (BB*NN) + n0 + nl*2;
    #pragma unroll
    for (int bp = 0; bp < 4; bp++) {
        float l0, h0, l1, h1;
        unpackf2(l0, h0, acc[0][bp]);
        unpackf2(l1, h1, acc[1][bp]);
        int b0 = bg*8 + bp*2;
        *(float2*)(dst + (size_t)b0*NN)     = make_float2(l0, l1);
        *(float2*)(dst + (size_t)(b0+1)*NN) = make_float2(h0, h1);
    }
}

// ---------- K5: deterministic reduce + bias ----------
__global__ void k5_reduce(const float* __restrict__ bq, float* __restrict__ q) {
    int idx = blockIdx.x * 256 + threadIdx.x;   // 64 blocks x 256 = 16384
    float s = bq[idx & (NN - 1)];
    #pragma unroll 16
    for (int p = 0; p < KSPLIT; p++)
        s += g_part[(size_t)p * (BB*NN) + idx];
    q[idx] = s;
}

extern "C" void kernel_launch(void* const* d_in, const int* in_sizes, int n_in,
                              void* d_out, int out_size) {
    const float* xv     = (const float*)d_in[0];
    const float* adj    = (const float*)d_in[1];
    const float* Wheads = (const float*)d_in[2];
    const float* a1     = (const float*)d_in[3];
    const float* a2     = (const float*)d_in[4];
    const float* Wout   = (const float*)d_in[5];
    const float* a1o    = (const float*)d_in[6];
    const float* a2o    = (const float*)d_in[7];
    const float* Wq     = (const float*)d_in[8];
    const float* bq     = (const float*)d_in[9];
    float* q = (float*)d_out;

    k1_prep<<<128, 128>>>(xv, Wheads, a1, a2);
    k2_gat<<<PREF + BB*NN/8, 256>>>(adj, Wout, a1o, a2o, Wq);
    k3_out<<<BB*NN/8, 256>>>();
    k4_gemm<<<K4NT*KSPLIT, 256>>>(Wq);
    k5_reduce<<<64, 256>>>(bq, q);
}